// round 1
// baseline (speedup 1.0000x reference)
#include <cuda_runtime.h>

#define B_ 8
#define N_ 1024
#define C_ 768
#define H_ 12
#define HD 64
#define M_TOT (B_*N_)    // 8192
#define QKV_N (3*C_)     // 2304
#define EPS 1e-6f
#define EPSN (1e-6f/1024.0f)

// Scratch (device-global: allocation inside kernel_launch is forbidden)
__device__ float g_q[B_*H_*N_*HD];     // (B,H,N,64)
__device__ float g_k[B_*H_*N_*HD];
__device__ float g_v[B_*H_*N_*HD];
__device__ float g_aout[M_TOT*C_];     // (B,N,C) attention output

// ---------------------------------------------------------------------------
// QKV GEMM: qkv[m, col] = sum_k x[m,k] * Wqkv[col,k]; scatter into q/k/v
// 64x64 tile, BK=16, 256 threads, 4x4 per thread.
// ---------------------------------------------------------------------------
__global__ __launch_bounds__(256) void qkv_gemm_kernel(const float* __restrict__ x,
                                                       const float* __restrict__ W) {
    __shared__ float As[16][65];
    __shared__ float Bs[16][65];
    const int bm = blockIdx.y * 64;
    const int bn = blockIdx.x * 64;
    const int tid = threadIdx.x;
    const int tx = tid & 15, ty = tid >> 4;
    const int lc = tid & 15;   // k within tile
    const int lr = tid >> 4;   // row base

    float acc[4][4] = {};

    for (int k0 = 0; k0 < C_; k0 += 16) {
        #pragma unroll
        for (int i = 0; i < 4; i++) {
            As[lc][lr + 16*i] = x[(bm + lr + 16*i) * C_ + k0 + lc];
            Bs[lc][lr + 16*i] = W[(bn + lr + 16*i) * C_ + k0 + lc];
        }
        __syncthreads();
        #pragma unroll
        for (int kk = 0; kk < 16; kk++) {
            float a[4], bb[4];
            #pragma unroll
            for (int i = 0; i < 4; i++) a[i]  = As[kk][ty*4 + i];
            #pragma unroll
            for (int j = 0; j < 4; j++) bb[j] = Bs[kk][tx*4 + j];
            #pragma unroll
            for (int i = 0; i < 4; i++)
                #pragma unroll
                for (int j = 0; j < 4; j++) acc[i][j] += a[i] * bb[j];
        }
        __syncthreads();
    }

    // Scatter: each 64-wide column tile lies entirely in one head of one of q/k/v
    const int which = bn / C_;            // 0=q, 1=k, 2=v
    const int cc0 = bn - which * C_;
    const int h = cc0 >> 6;
    float* dst = (which == 0) ? g_q : (which == 1) ? g_k : g_v;
    #pragma unroll
    for (int i = 0; i < 4; i++) {
        int m = bm + ty*4 + i;
        int b = m >> 10, n = m & 1023;
        float* row = dst + (((b*H_ + h) * N_) + n) * HD;
        #pragma unroll
        for (int j = 0; j < 4; j++) row[tx*4 + j] = acc[i][j];
    }
}

// ---------------------------------------------------------------------------
// Policy-masked flash attention.
// Block = (query-tile of 64, b*H+h). 256 threads, 4 queries x 4 (key|dim) each.
// smem: Qs, Ks, Vs, Ps (64x64 each) + polK (64) -> 65792 B dynamic.
// ---------------------------------------------------------------------------
__global__ __launch_bounds__(256) void attn_kernel(const float* __restrict__ policy) {
    extern __shared__ float smem[];
    float* Qs   = smem;              // [q][d]
    float* Ks   = smem + 4096;       // [key][d]
    float* Vs   = smem + 8192;       // [key][d]
    float* Ps   = smem + 12288;      // [q][key]
    float* polK = smem + 16384;      // [key]

    const int qt = blockIdx.x;       // 0..15
    const int bh = blockIdx.y;       // 0..95
    const int b  = bh / H_;
    const int h  = bh - b * H_;
    const int tid = threadIdx.x;
    const int tx = tid & 15, ty = tid >> 4;
    const int qrow = ty * 4;
    const int dcol = tx * 4;         // key-col in S phase, dim-col in PV phase
    const int nq0  = qt * 64 + qrow;

    const float scale = 0.125f;      // 64^-0.5
    const int qbase = (bh * N_ + qt * 64) * HD;

    #pragma unroll
    for (int it = 0; it < 16; it++) {
        int l = tid + it * 256;
        Qs[l] = g_q[qbase + l] * scale;
    }
    float polq[4];
    #pragma unroll
    for (int i = 0; i < 4; i++) polq[i] = policy[b * N_ + nq0 + i];

    float m_[4], l_[4], O[4][4] = {}, vsum[4] = {};
    #pragma unroll
    for (int i = 0; i < 4; i++) { m_[i] = -1e30f; l_[i] = 0.f; }

    for (int kt = 0; kt < 16; kt++) {
        const int kbase = (bh * N_ + kt * 64) * HD;
        #pragma unroll
        for (int it = 0; it < 16; it++) {
            int l = tid + it * 256;
            Ks[l] = g_k[kbase + l];
            Vs[l] = g_v[kbase + l];
        }
        if (tid < 64) polK[tid] = policy[b * N_ + kt * 64 + tid];
        __syncthreads();

        // S = (Q*scale) K^T  (raw, unmasked — reference maxes before masking)
        float S[4][4] = {};
        #pragma unroll
        for (int d = 0; d < 64; d++) {
            float a[4], bb[4];
            #pragma unroll
            for (int i = 0; i < 4; i++) a[i]  = Qs[(qrow + i) * 64 + d];
            #pragma unroll
            for (int j = 0; j < 4; j++) bb[j] = Ks[(dcol + j) * 64 + d];
            #pragma unroll
            for (int i = 0; i < 4; i++)
                #pragma unroll
                for (int j = 0; j < 4; j++) S[i][j] += a[i] * bb[j];
        }

        // Unmasked row max across the 16-lane tx group
        float mnew[4], resc[4];
        #pragma unroll
        for (int i = 0; i < 4; i++) {
            float t = fmaxf(fmaxf(S[i][0], S[i][1]), fmaxf(S[i][2], S[i][3]));
            t = fmaxf(t, __shfl_xor_sync(0xffffffffu, t, 1));
            t = fmaxf(t, __shfl_xor_sync(0xffffffffu, t, 2));
            t = fmaxf(t, __shfl_xor_sync(0xffffffffu, t, 4));
            t = fmaxf(t, __shfl_xor_sync(0xffffffffu, t, 8));
            mnew[i] = fmaxf(m_[i], t);
            resc[i] = __expf(m_[i] - mnew[i]);
        }

        // P = exp(S - mnew) * mask;  mask = (m==n) ? 1 : p_q * p_k
        float psum[4] = {};
        #pragma unroll
        for (int i = 0; i < 4; i++) {
            const int nq = nq0 + i;
            #pragma unroll
            for (int j = 0; j < 4; j++) {
                const int mk = kt * 64 + dcol + j;
                const float mask = (mk == nq) ? 1.0f : polq[i] * polK[dcol + j];
                const float p = __expf(S[i][j] - mnew[i]) * mask;
                psum[i] += p;
                Ps[(qrow + i) * 64 + dcol + j] = p;
            }
        }
        #pragma unroll
        for (int i = 0; i < 4; i++) {
            float s = psum[i];
            s += __shfl_xor_sync(0xffffffffu, s, 1);
            s += __shfl_xor_sync(0xffffffffu, s, 2);
            s += __shfl_xor_sync(0xffffffffu, s, 4);
            s += __shfl_xor_sync(0xffffffffu, s, 8);
            l_[i] = l_[i] * resc[i] + s;
            m_[i] = mnew[i];
            #pragma unroll
            for (int j = 0; j < 4; j++) O[i][j] *= resc[i];
        }
        __syncthreads();   // Ps fully written before PV

        // O += P V ; vsum += V (unmasked V row-sum for the eps/N term)
        #pragma unroll
        for (int kk = 0; kk < 64; kk++) {
            float vv[4];
            #pragma unroll
            for (int j = 0; j < 4; j++) vv[j] = Vs[kk * 64 + dcol + j];
            #pragma unroll
            for (int j = 0; j < 4; j++) vsum[j] += vv[j];
            #pragma unroll
            for (int i = 0; i < 4; i++) {
                const float p = Ps[(qrow + i) * 64 + kk];
                #pragma unroll
                for (int j = 0; j < 4; j++) O[i][j] += p * vv[j];
            }
        }
        __syncthreads();   // before Ks/Vs/Ps/polK are overwritten
    }

    // out = (O + (eps/N) * sumV) / (l + eps), written to (B,N,C) layout
    #pragma unroll
    for (int i = 0; i < 4; i++) {
        const float inv = 1.0f / (l_[i] + EPS);
        float* row = g_aout + (b * N_ + nq0 + i) * C_ + h * HD;
        #pragma unroll
        for (int j = 0; j < 4; j++)
            row[dcol + j] = (O[i][j] + EPSN * vsum[j]) * inv;
    }
}

// ---------------------------------------------------------------------------
// Output projection: out[m, j] = sum_k aout[m,k] * Wproj[j,k] + bproj[j]
// ---------------------------------------------------------------------------
__global__ __launch_bounds__(256) void proj_gemm_kernel(const float* __restrict__ W,
                                                        const float* __restrict__ bias,
                                                        float* __restrict__ out) {
    __shared__ float As[16][65];
    __shared__ float Bs[16][65];
    const int bm = blockIdx.y * 64;
    const int bn = blockIdx.x * 64;
    const int tid = threadIdx.x;
    const int tx = tid & 15, ty = tid >> 4;
    const int lc = tid & 15;
    const int lr = tid >> 4;

    float acc[4][4] = {};

    for (int k0 = 0; k0 < C_; k0 += 16) {
        #pragma unroll
        for (int i = 0; i < 4; i++) {
            As[lc][lr + 16*i] = g_aout[(bm + lr + 16*i) * C_ + k0 + lc];
            Bs[lc][lr + 16*i] = W[(bn + lr + 16*i) * C_ + k0 + lc];
        }
        __syncthreads();
        #pragma unroll
        for (int kk = 0; kk < 16; kk++) {
            float a[4], bb[4];
            #pragma unroll
            for (int i = 0; i < 4; i++) a[i]  = As[kk][ty*4 + i];
            #pragma unroll
            for (int j = 0; j < 4; j++) bb[j] = Bs[kk][tx*4 + j];
            #pragma unroll
            for (int i = 0; i < 4; i++)
                #pragma unroll
                for (int j = 0; j < 4; j++) acc[i][j] += a[i] * bb[j];
        }
        __syncthreads();
    }

    #pragma unroll
    for (int i = 0; i < 4; i++) {
        const int m = bm + ty*4 + i;
        #pragma unroll
        for (int j = 0; j < 4; j++) {
            const int col = bn + tx*4 + j;
            out[m * C_ + col] = acc[i][j] + bias[col];
        }
    }
}

// ---------------------------------------------------------------------------
extern "C" void kernel_launch(void* const* d_in, const int* in_sizes, int n_in,
                              void* d_out, int out_size) {
    const float* x      = (const float*)d_in[0];
    const float* policy = (const float*)d_in[1];
    const float* Wqkv   = (const float*)d_in[2];
    const float* Wproj  = (const float*)d_in[3];
    const float* bproj  = (const float*)d_in[4];
    float* out = (float*)d_out;

    qkv_gemm_kernel<<<dim3(QKV_N/64, M_TOT/64), 256>>>(x, Wqkv);

    cudaFuncSetAttribute(attn_kernel,
                         cudaFuncAttributeMaxDynamicSharedMemorySize, 65792);
    attn_kernel<<<dim3(16, 96), 256, 65792>>>(policy);

    proj_gemm_kernel<<<dim3(C_/64, M_TOT/64), 256>>>(Wproj, bproj, out);
}

// round 2
// speedup vs baseline: 1.0005x; 1.0005x over previous
#include <cuda_runtime.h>

#define B_ 8
#define N_ 1024
#define C_ 768
#define H_ 12
#define HD 64
#define M_TOT (B_*N_)    // 8192
#define QKV_N (3*C_)     // 2304
#define EPS 1e-6f
#define EPSN (1e-6f/1024.0f)

// Scratch (device-global: allocation inside kernel_launch is forbidden)
__device__ float g_q[B_*H_*N_*HD];     // (B,H,N,64)
__device__ float g_k[B_*H_*N_*HD];
__device__ float g_v[B_*H_*N_*HD];
__device__ float g_aout[M_TOT*C_];     // (B,N,C) attention output

// ---------------------------------------------------------------------------
// QKV GEMM: qkv[m, col] = sum_k x[m,k] * Wqkv[col,k]; scatter into q/k/v
// 64x64 tile, BK=16, 256 threads, 4x4 per thread.
// ---------------------------------------------------------------------------
__global__ __launch_bounds__(256) void qkv_gemm_kernel(const float* __restrict__ x,
                                                       const float* __restrict__ W) {
    __shared__ float As[16][65];
    __shared__ float Bs[16][65];
    const int bm = blockIdx.y * 64;
    const int bn = blockIdx.x * 64;
    const int tid = threadIdx.x;
    const int tx = tid & 15, ty = tid >> 4;
    const int lc = tid & 15;   // k within tile
    const int lr = tid >> 4;   // row base

    float acc[4][4] = {};

    for (int k0 = 0; k0 < C_; k0 += 16) {
        #pragma unroll
        for (int i = 0; i < 4; i++) {
            As[lc][lr + 16*i] = x[(bm + lr + 16*i) * C_ + k0 + lc];
            Bs[lc][lr + 16*i] = W[(bn + lr + 16*i) * C_ + k0 + lc];
        }
        __syncthreads();
        #pragma unroll
        for (int kk = 0; kk < 16; kk++) {
            float a[4], bb[4];
            #pragma unroll
            for (int i = 0; i < 4; i++) a[i]  = As[kk][ty*4 + i];
            #pragma unroll
            for (int j = 0; j < 4; j++) bb[j] = Bs[kk][tx*4 + j];
            #pragma unroll
            for (int i = 0; i < 4; i++)
                #pragma unroll
                for (int j = 0; j < 4; j++) acc[i][j] += a[i] * bb[j];
        }
        __syncthreads();
    }

    // Scatter: each 64-wide column tile lies entirely in one head of one of q/k/v
    const int which = bn / C_;            // 0=q, 1=k, 2=v
    const int cc0 = bn - which * C_;
    const int h = cc0 >> 6;
    float* dst = (which == 0) ? g_q : (which == 1) ? g_k : g_v;
    #pragma unroll
    for (int i = 0; i < 4; i++) {
        int m = bm + ty*4 + i;
        int b = m >> 10, n = m & 1023;
        float* row = dst + (((b*H_ + h) * N_) + n) * HD;
        #pragma unroll
        for (int j = 0; j < 4; j++) row[tx*4 + j] = acc[i][j];
    }
}

// ---------------------------------------------------------------------------
// Policy-masked flash attention.
// Block = (query-tile of 64, b*H+h). 256 threads, 4 queries x 4 (key|dim) each.
// smem: Qs, Ks, Vs, Ps (64x64 each) + polK (64) -> 65792 B dynamic.
// ---------------------------------------------------------------------------
__global__ __launch_bounds__(256) void attn_kernel(const float* __restrict__ policy) {
    extern __shared__ float smem[];
    float* Qs   = smem;              // [q][d]
    float* Ks   = smem + 4096;       // [key][d]
    float* Vs   = smem + 8192;       // [key][d]
    float* Ps   = smem + 12288;      // [q][key]
    float* polK = smem + 16384;      // [key]

    const int qt = blockIdx.x;       // 0..15
    const int bh = blockIdx.y;       // 0..95
    const int b  = bh / H_;
    const int h  = bh - b * H_;
    const int tid = threadIdx.x;
    const int tx = tid & 15, ty = tid >> 4;
    const int qrow = ty * 4;
    const int dcol = tx * 4;         // key-col in S phase, dim-col in PV phase
    const int nq0  = qt * 64 + qrow;

    const float scale = 0.125f;      // 64^-0.5
    const int qbase = (bh * N_ + qt * 64) * HD;

    #pragma unroll
    for (int it = 0; it < 16; it++) {
        int l = tid + it * 256;
        Qs[l] = g_q[qbase + l] * scale;
    }
    float polq[4];
    #pragma unroll
    for (int i = 0; i < 4; i++) polq[i] = policy[b * N_ + nq0 + i];

    float m_[4], l_[4], O[4][4] = {}, vsum[4] = {};
    #pragma unroll
    for (int i = 0; i < 4; i++) { m_[i] = -1e30f; l_[i] = 0.f; }

    for (int kt = 0; kt < 16; kt++) {
        const int kbase = (bh * N_ + kt * 64) * HD;
        #pragma unroll
        for (int it = 0; it < 16; it++) {
            int l = tid + it * 256;
            Ks[l] = g_k[kbase + l];
            Vs[l] = g_v[kbase + l];
        }
        if (tid < 64) polK[tid] = policy[b * N_ + kt * 64 + tid];
        __syncthreads();

        // S = (Q*scale) K^T  (raw, unmasked — reference maxes before masking)
        float S[4][4] = {};
        #pragma unroll
        for (int d = 0; d < 64; d++) {
            float a[4], bb[4];
            #pragma unroll
            for (int i = 0; i < 4; i++) a[i]  = Qs[(qrow + i) * 64 + d];
            #pragma unroll
            for (int j = 0; j < 4; j++) bb[j] = Ks[(dcol + j) * 64 + d];
            #pragma unroll
            for (int i = 0; i < 4; i++)
                #pragma unroll
                for (int j = 0; j < 4; j++) S[i][j] += a[i] * bb[j];
        }

        // Unmasked row max across the 16-lane tx group
        float mnew[4], resc[4];
        #pragma unroll
        for (int i = 0; i < 4; i++) {
            float t = fmaxf(fmaxf(S[i][0], S[i][1]), fmaxf(S[i][2], S[i][3]));
            t = fmaxf(t, __shfl_xor_sync(0xffffffffu, t, 1));
            t = fmaxf(t, __shfl_xor_sync(0xffffffffu, t, 2));
            t = fmaxf(t, __shfl_xor_sync(0xffffffffu, t, 4));
            t = fmaxf(t, __shfl_xor_sync(0xffffffffu, t, 8));
            mnew[i] = fmaxf(m_[i], t);
            resc[i] = __expf(m_[i] - mnew[i]);
        }

        // P = exp(S - mnew) * mask;  mask = (m==n) ? 1 : p_q * p_k
        float psum[4] = {};
        #pragma unroll
        for (int i = 0; i < 4; i++) {
            const int nq = nq0 + i;
            #pragma unroll
            for (int j = 0; j < 4; j++) {
                const int mk = kt * 64 + dcol + j;
                const float mask = (mk == nq) ? 1.0f : polq[i] * polK[dcol + j];
                const float p = __expf(S[i][j] - mnew[i]) * mask;
                psum[i] += p;
                Ps[(qrow + i) * 64 + dcol + j] = p;
            }
        }
        #pragma unroll
        for (int i = 0; i < 4; i++) {
            float s = psum[i];
            s += __shfl_xor_sync(0xffffffffu, s, 1);
            s += __shfl_xor_sync(0xffffffffu, s, 2);
            s += __shfl_xor_sync(0xffffffffu, s, 4);
            s += __shfl_xor_sync(0xffffffffu, s, 8);
            l_[i] = l_[i] * resc[i] + s;
            m_[i] = mnew[i];
            #pragma unroll
            for (int j = 0; j < 4; j++) O[i][j] *= resc[i];
        }
        __syncthreads();   // Ps fully written before PV

        // O += P V ; vsum += V (unmasked V row-sum for the eps/N term)
        #pragma unroll
        for (int kk = 0; kk < 64; kk++) {
            float vv[4];
            #pragma unroll
            for (int j = 0; j < 4; j++) vv[j] = Vs[kk * 64 + dcol + j];
            #pragma unroll
            for (int j = 0; j < 4; j++) vsum[j] += vv[j];
            #pragma unroll
            for (int i = 0; i < 4; i++) {
                const float p = Ps[(qrow + i) * 64 + kk];
                #pragma unroll
                for (int j = 0; j < 4; j++) O[i][j] += p * vv[j];
            }
        }
        __syncthreads();   // before Ks/Vs/Ps/polK are overwritten
    }

    // out = (O + (eps/N) * sumV) / (l + eps), written to (B,N,C) layout
    #pragma unroll
    for (int i = 0; i < 4; i++) {
        const float inv = 1.0f / (l_[i] + EPS);
        float* row = g_aout + (b * N_ + nq0 + i) * C_ + h * HD;
        #pragma unroll
        for (int j = 0; j < 4; j++)
            row[dcol + j] = (O[i][j] + EPSN * vsum[j]) * inv;
    }
}

// ---------------------------------------------------------------------------
// Output projection: out[m, j] = sum_k aout[m,k] * Wproj[j,k] + bproj[j]
// ---------------------------------------------------------------------------
__global__ __launch_bounds__(256) void proj_gemm_kernel(const float* __restrict__ W,
                                                        const float* __restrict__ bias,
                                                        float* __restrict__ out) {
    __shared__ float As[16][65];
    __shared__ float Bs[16][65];
    const int bm = blockIdx.y * 64;
    const int bn = blockIdx.x * 64;
    const int tid = threadIdx.x;
    const int tx = tid & 15, ty = tid >> 4;
    const int lc = tid & 15;
    const int lr = tid >> 4;

    float acc[4][4] = {};

    for (int k0 = 0; k0 < C_; k0 += 16) {
        #pragma unroll
        for (int i = 0; i < 4; i++) {
            As[lc][lr + 16*i] = g_aout[(bm + lr + 16*i) * C_ + k0 + lc];
            Bs[lc][lr + 16*i] = W[(bn + lr + 16*i) * C_ + k0 + lc];
        }
        __syncthreads();
        #pragma unroll
        for (int kk = 0; kk < 16; kk++) {
            float a[4], bb[4];
            #pragma unroll
            for (int i = 0; i < 4; i++) a[i]  = As[kk][ty*4 + i];
            #pragma unroll
            for (int j = 0; j < 4; j++) bb[j] = Bs[kk][tx*4 + j];
            #pragma unroll
            for (int i = 0; i < 4; i++)
                #pragma unroll
                for (int j = 0; j < 4; j++) acc[i][j] += a[i] * bb[j];
        }
        __syncthreads();
    }

    #pragma unroll
    for (int i = 0; i < 4; i++) {
        const int m = bm + ty*4 + i;
        #pragma unroll
        for (int j = 0; j < 4; j++) {
            const int col = bn + tx*4 + j;
            out[m * C_ + col] = acc[i][j] + bias[col];
        }
    }
}

// ---------------------------------------------------------------------------
extern "C" void kernel_launch(void* const* d_in, const int* in_sizes, int n_in,
                              void* d_out, int out_size) {
    const float* x      = (const float*)d_in[0];
    const float* policy = (const float*)d_in[1];
    const float* Wqkv   = (const float*)d_in[2];
    const float* Wproj  = (const float*)d_in[3];
    const float* bproj  = (const float*)d_in[4];
    float* out = (float*)d_out;

    qkv_gemm_kernel<<<dim3(QKV_N/64, M_TOT/64), 256>>>(x, Wqkv);

    cudaFuncSetAttribute(attn_kernel,
                         cudaFuncAttributeMaxDynamicSharedMemorySize, 65792);
    attn_kernel<<<dim3(16, 96), 256, 65792>>>(policy);

    proj_gemm_kernel<<<dim3(C_/64, M_TOT/64), 256>>>(Wproj, bproj, out);
}

// round 3
// speedup vs baseline: 1.9220x; 1.9210x over previous
#include <cuda_runtime.h>

#define B_ 8
#define N_ 1024
#define C_ 768
#define H_ 12
#define HD 64
#define M_TOT (B_*N_)    // 8192
#define QKV_N (3*C_)     // 2304
#define EPS 1e-6f
#define EPSN (1e-6f/1024.0f)
#define SC2E 0.18033688011112042f   // (1/sqrt(64)) * log2(e)

// ---------------------------------------------------------------------------
// packed f32x2 helpers (Blackwell fp32x2 pipe — 2 FMA per instruction)
// ---------------------------------------------------------------------------
__device__ __forceinline__ float2 ffma2(float2 a, float2 b, float2 c) {
    union U { float2 f; unsigned long long u; };
    U A, Bx, Cx, D; A.f = a; Bx.f = b; Cx.f = c;
    asm("fma.rn.f32x2 %0, %1, %2, %3;" : "=l"(D.u) : "l"(A.u), "l"(Bx.u), "l"(Cx.u));
    return D.f;
}
__device__ __forceinline__ float2 add2(float2 a, float2 b) {
    union U { float2 f; unsigned long long u; };
    U A, Bx, D; A.f = a; Bx.f = b;
    asm("add.rn.f32x2 %0, %1, %2;" : "=l"(D.u) : "l"(A.u), "l"(Bx.u));
    return D.f;
}
__device__ __forceinline__ float2 mul2(float2 a, float2 b) {
    union U { float2 f; unsigned long long u; };
    U A, Bx, D; A.f = a; Bx.f = b;
    asm("mul.rn.f32x2 %0, %1, %2;" : "=l"(D.u) : "l"(A.u), "l"(Bx.u));
    return D.f;
}

// 2^x via FFMA-pipe polynomial (keeps MUFU free; rel err ~3e-6). x <= ~0.
__device__ __forceinline__ float exp2_fast(float x) {
    float t = fmaxf(x, -80.f);
    float z = t + 12582912.f;              // 1.5*2^23: round-to-nearest trick
    int   n = __float_as_int(z) - 0x4B400000;
    float f = t - (z - 12582912.f);        // f in [-0.5, 0.5]
    float p = 1.3333558e-3f;
    p = fmaf(p, f, 9.618129e-3f);
    p = fmaf(p, f, 5.5504109e-2f);
    p = fmaf(p, f, 2.4022651e-1f);
    p = fmaf(p, f, 6.9314718e-1f);
    p = fmaf(p, f, 1.0f);
    return __int_as_float(__float_as_int(p) + (n << 23));
}

// Scratch
__device__ float g_q[B_*H_*N_*HD];     // (B,H,N,64)
__device__ float g_k[B_*H_*N_*HD];
__device__ float g_v[B_*H_*N_*HD];
__device__ float g_aout[M_TOT*C_];     // (B,N,C)

// ---------------------------------------------------------------------------
// GEMM core: 64x64 tile, BK=16, 256 threads, 4x4 micro (strided tx+16j),
// FFMA2 packed along K. As/Bs pitch 18 -> conflict-free strided row reads.
// ---------------------------------------------------------------------------
#define GP 18

// QKV GEMM + scatter to (B,H,N,64)
__global__ __launch_bounds__(256) void qkv_gemm_kernel(const float* __restrict__ x,
                                                       const float* __restrict__ W) {
    __shared__ float As[64*GP];
    __shared__ float Bs[64*GP];
    const int bm = blockIdx.y * 64;
    const int bn = blockIdx.x * 64;
    const int tid = threadIdx.x;
    const int tx = tid & 15, ty = tid >> 4;
    const int r  = tid >> 2, c4 = tid & 3;          // loader mapping

    const float* gA = x + (bm + r) * C_ + c4 * 4;
    const float* gB = W + (bn + r) * C_ + c4 * 4;
    float4 ra = *(const float4*)gA;
    float4 rb = *(const float4*)gB;

    float2 acc[4][4];
    #pragma unroll
    for (int i = 0; i < 4; i++)
        #pragma unroll
        for (int j = 0; j < 4; j++) acc[i][j] = make_float2(0.f, 0.f);

    for (int k0 = 0; k0 < C_; k0 += 16) {
        const int sb = r * GP + c4 * 4;
        As[sb+0] = ra.x; As[sb+1] = ra.y; As[sb+2] = ra.z; As[sb+3] = ra.w;
        Bs[sb+0] = rb.x; Bs[sb+1] = rb.y; Bs[sb+2] = rb.z; Bs[sb+3] = rb.w;
        __syncthreads();
        if (k0 + 16 < C_) {
            ra = *(const float4*)(gA + k0 + 16);
            rb = *(const float4*)(gB + k0 + 16);
        }
        #pragma unroll
        for (int kk = 0; kk < 8; kk++) {
            float2 a2[4], b2[4];
            #pragma unroll
            for (int i = 0; i < 4; i++) a2[i] = *(const float2*)&As[(ty + 16*i)*GP + kk*2];
            #pragma unroll
            for (int j = 0; j < 4; j++) b2[j] = *(const float2*)&Bs[(tx + 16*j)*GP + kk*2];
            #pragma unroll
            for (int i = 0; i < 4; i++)
                #pragma unroll
                for (int j = 0; j < 4; j++) acc[i][j] = ffma2(a2[i], b2[j], acc[i][j]);
        }
        __syncthreads();
    }

    const int which = bn / C_;                 // 0=q,1=k,2=v
    const int h = (bn - which * C_) >> 6;
    float* dst = (which == 0) ? g_q : (which == 1) ? g_k : g_v;
    #pragma unroll
    for (int i = 0; i < 4; i++) {
        const int m = bm + ty + 16*i;
        const int b = m >> 10, n = m & 1023;
        float* row = dst + (((b*H_ + h) * N_) + n) * HD;
        #pragma unroll
        for (int j = 0; j < 4; j++) row[tx + 16*j] = acc[i][j].x + acc[i][j].y;
    }
}

// Output projection
__global__ __launch_bounds__(256) void proj_gemm_kernel(const float* __restrict__ W,
                                                        const float* __restrict__ bias,
                                                        float* __restrict__ out) {
    __shared__ float As[64*GP];
    __shared__ float Bs[64*GP];
    const int bm = blockIdx.y * 64;
    const int bn = blockIdx.x * 64;
    const int tid = threadIdx.x;
    const int tx = tid & 15, ty = tid >> 4;
    const int r  = tid >> 2, c4 = tid & 3;

    const float* gA = g_aout + (bm + r) * C_ + c4 * 4;
    const float* gB = W + (bn + r) * C_ + c4 * 4;
    float4 ra = *(const float4*)gA;
    float4 rb = *(const float4*)gB;

    float2 acc[4][4];
    #pragma unroll
    for (int i = 0; i < 4; i++)
        #pragma unroll
        for (int j = 0; j < 4; j++) acc[i][j] = make_float2(0.f, 0.f);

    for (int k0 = 0; k0 < C_; k0 += 16) {
        const int sb = r * GP + c4 * 4;
        As[sb+0] = ra.x; As[sb+1] = ra.y; As[sb+2] = ra.z; As[sb+3] = ra.w;
        Bs[sb+0] = rb.x; Bs[sb+1] = rb.y; Bs[sb+2] = rb.z; Bs[sb+3] = rb.w;
        __syncthreads();
        if (k0 + 16 < C_) {
            ra = *(const float4*)(gA + k0 + 16);
            rb = *(const float4*)(gB + k0 + 16);
        }
        #pragma unroll
        for (int kk = 0; kk < 8; kk++) {
            float2 a2[4], b2[4];
            #pragma unroll
            for (int i = 0; i < 4; i++) a2[i] = *(const float2*)&As[(ty + 16*i)*GP + kk*2];
            #pragma unroll
            for (int j = 0; j < 4; j++) b2[j] = *(const float2*)&Bs[(tx + 16*j)*GP + kk*2];
            #pragma unroll
            for (int i = 0; i < 4; i++)
                #pragma unroll
                for (int j = 0; j < 4; j++) acc[i][j] = ffma2(a2[i], b2[j], acc[i][j]);
        }
        __syncthreads();
    }

    #pragma unroll
    for (int i = 0; i < 4; i++) {
        const int m = bm + ty + 16*i;
        #pragma unroll
        for (int j = 0; j < 4; j++) {
            const int col = bn + tx + 16*j;
            out[m * C_ + col] = acc[i][j].x + acc[i][j].y + bias[col];
        }
    }
}

// ---------------------------------------------------------------------------
// Policy-masked flash attention, log2-domain softmax, FFMA2 everywhere.
// Block = (64-query tile, b*H+h). 256 threads: thread = (tx,ty),
//   S phase:  q rows {ty+16i}, keys {tx+16j}   (packed along d)
//   PV phase: q rows {ty+16i}, dims {tx+16j}   (packed along key, V transposed)
// smem (floats): Qs[64*66] Ks[64*66] VsT[64*66] Ps[64*64] = 67072 B dynamic.
// ---------------------------------------------------------------------------
#define AP 66
__global__ __launch_bounds__(256) void attn_kernel(const float* __restrict__ policy) {
    extern __shared__ float smem[];
    float* Qs  = smem;                 // [q][d]   pitch 66
    float* Ks  = smem + 64*AP;         // [key][d] pitch 66
    float* VsT = smem + 2*64*AP;       // [d][key] pitch 66
    float* Ps  = smem + 3*64*AP;       // [q][key] pitch 64

    const int qt = blockIdx.x;         // 0..15
    const int bh = blockIdx.y;         // 0..95
    const int b  = bh / H_;
    const int h  = bh - b * H_;
    const int tid = threadIdx.x;
    const int tx = tid & 15, ty = tid >> 4;

    const int qbase = (bh * N_ + qt * 64) * HD;
    const int lr = tid >> 4;           // 0..15 (loader row base)
    const int ld4 = tid & 15;

    // Q tile (scaled by scale*log2e)
    #pragma unroll
    for (int it = 0; it < 4; it++) {
        const int rr = lr + 16*it;
        float4 v = *(const float4*)(g_q + qbase + rr*HD + ld4*4);
        float* d = &Qs[rr*AP + ld4*4];
        d[0] = v.x*SC2E; d[1] = v.y*SC2E; d[2] = v.z*SC2E; d[3] = v.w*SC2E;
    }

    float polq[4];
    #pragma unroll
    for (int i = 0; i < 4; i++) polq[i] = policy[b*N_ + qt*64 + ty + 16*i];

    float m_[4], l_[4];
    float2 O2[4][4], vsum2[4];
    #pragma unroll
    for (int i = 0; i < 4; i++) { m_[i] = -1e30f; l_[i] = 0.f; }
    #pragma unroll
    for (int i = 0; i < 4; i++)
        #pragma unroll
        for (int j = 0; j < 4; j++) O2[i][j] = make_float2(0.f, 0.f);
    #pragma unroll
    for (int j = 0; j < 4; j++) vsum2[j] = make_float2(0.f, 0.f);

    for (int kt = 0; kt < 16; kt++) {
        const int kbase = (bh * N_ + kt * 64) * HD;
        // K natural, V transposed into smem
        #pragma unroll
        for (int it = 0; it < 4; it++) {
            const int rr = lr + 16*it;
            float4 kv = *(const float4*)(g_k + kbase + rr*HD + ld4*4);
            float* d = &Ks[rr*AP + ld4*4];
            d[0] = kv.x; d[1] = kv.y; d[2] = kv.z; d[3] = kv.w;
            float4 vv = *(const float4*)(g_v + kbase + rr*HD + ld4*4);
            VsT[(ld4*4+0)*AP + rr] = vv.x;
            VsT[(ld4*4+1)*AP + rr] = vv.y;
            VsT[(ld4*4+2)*AP + rr] = vv.z;
            VsT[(ld4*4+3)*AP + rr] = vv.w;
        }
        float polk[4];
        #pragma unroll
        for (int j = 0; j < 4; j++) polk[j] = policy[b*N_ + kt*64 + tx + 16*j];
        __syncthreads();

        // S = Q K^T (log2 units), packed along d
        float2 S2[4][4];
        #pragma unroll
        for (int i = 0; i < 4; i++)
            #pragma unroll
            for (int j = 0; j < 4; j++) S2[i][j] = make_float2(0.f, 0.f);
        #pragma unroll
        for (int d2 = 0; d2 < 32; d2++) {
            float2 q2[4], k2[4];
            #pragma unroll
            for (int i = 0; i < 4; i++) q2[i] = *(const float2*)&Qs[(ty + 16*i)*AP + d2*2];
            #pragma unroll
            for (int j = 0; j < 4; j++) k2[j] = *(const float2*)&Ks[(tx + 16*j)*AP + d2*2];
            #pragma unroll
            for (int i = 0; i < 4; i++)
                #pragma unroll
                for (int j = 0; j < 4; j++) S2[i][j] = ffma2(q2[i], k2[j], S2[i][j]);
        }
        float S[4][4];
        #pragma unroll
        for (int i = 0; i < 4; i++)
            #pragma unroll
            for (int j = 0; j < 4; j++) S[i][j] = S2[i][j].x + S2[i][j].y;

        // unmasked running max (log2 domain), rescale
        float mnew[4], resc[4];
        #pragma unroll
        for (int i = 0; i < 4; i++) {
            float t = fmaxf(fmaxf(S[i][0], S[i][1]), fmaxf(S[i][2], S[i][3]));
            t = fmaxf(t, __shfl_xor_sync(0xffffffffu, t, 1));
            t = fmaxf(t, __shfl_xor_sync(0xffffffffu, t, 2));
            t = fmaxf(t, __shfl_xor_sync(0xffffffffu, t, 4));
            t = fmaxf(t, __shfl_xor_sync(0xffffffffu, t, 8));
            mnew[i] = fmaxf(m_[i], t);
            resc[i] = exp2_fast(m_[i] - mnew[i]);
        }

        // P = 2^(S-m) * mask
        float psum[4];
        #pragma unroll
        for (int i = 0; i < 4; i++) {
            const int nq = qt*64 + ty + 16*i;
            psum[i] = 0.f;
            #pragma unroll
            for (int j = 0; j < 4; j++) {
                const int mk = kt*64 + tx + 16*j;
                const float mask = (mk == nq) ? 1.0f : polq[i] * polk[j];
                const float p = exp2_fast(S[i][j] - mnew[i]) * mask;
                psum[i] += p;
                Ps[(ty + 16*i)*64 + tx + 16*j] = p;
            }
        }
        #pragma unroll
        for (int i = 0; i < 4; i++) {
            float s = psum[i];
            s += __shfl_xor_sync(0xffffffffu, s, 1);
            s += __shfl_xor_sync(0xffffffffu, s, 2);
            s += __shfl_xor_sync(0xffffffffu, s, 4);
            s += __shfl_xor_sync(0xffffffffu, s, 8);
            l_[i] = l_[i] * resc[i] + s;
            m_[i] = mnew[i];
            const float2 r2 = make_float2(resc[i], resc[i]);
            #pragma unroll
            for (int j = 0; j < 4; j++) O2[i][j] = mul2(O2[i][j], r2);
        }
        __syncthreads();   // Ps ready

        // O += P V, packed along key; vsum += V rowsum
        #pragma unroll
        for (int k2i = 0; k2i < 32; k2i++) {
            float2 p2[4], v2[4];
            #pragma unroll
            for (int i = 0; i < 4; i++) p2[i] = *(const float2*)&Ps[(ty + 16*i)*64 + k2i*2];
            #pragma unroll
            for (int j = 0; j < 4; j++) v2[j] = *(const float2*)&VsT[(tx + 16*j)*AP + k2i*2];
            #pragma unroll
            for (int j = 0; j < 4; j++) vsum2[j] = add2(vsum2[j], v2[j]);
            #pragma unroll
            for (int i = 0; i < 4; i++)
                #pragma unroll
                for (int j = 0; j < 4; j++) O2[i][j] = ffma2(p2[i], v2[j], O2[i][j]);
        }
        __syncthreads();   // before tiles/Ps overwritten
    }

    #pragma unroll
    for (int i = 0; i < 4; i++) {
        const float inv = 1.0f / (l_[i] + EPS);
        float* row = g_aout + (b*N_ + qt*64 + ty + 16*i) * C_ + h * HD;
        #pragma unroll
        for (int j = 0; j < 4; j++) {
            const float vs = vsum2[j].x + vsum2[j].y;
            row[tx + 16*j] = (O2[i][j].x + O2[i][j].y + EPSN * vs) * inv;
        }
    }
}

// ---------------------------------------------------------------------------
extern "C" void kernel_launch(void* const* d_in, const int* in_sizes, int n_in,
                              void* d_out, int out_size) {
    const float* x      = (const float*)d_in[0];
    const float* policy = (const float*)d_in[1];
    const float* Wqkv   = (const float*)d_in[2];
    const float* Wproj  = (const float*)d_in[3];
    const float* bproj  = (const float*)d_in[4];
    float* out = (float*)d_out;

    qkv_gemm_kernel<<<dim3(QKV_N/64, M_TOT/64), 256>>>(x, Wqkv);

    cudaFuncSetAttribute(attn_kernel,
                         cudaFuncAttributeMaxDynamicSharedMemorySize, 67072);
    attn_kernel<<<dim3(16, 96), 256, 67072>>>(policy);

    proj_gemm_kernel<<<dim3(C_/64, M_TOT/64), 256>>>(Wproj, bproj, out);
}